// round 4
// baseline (speedup 1.0000x reference)
#include <cuda_runtime.h>

#define B_   32
#define T_   12
#define N_   512
#define E_   10
#define CI   64
#define CO   64
#define RTOT 192                 // K*CI
#define THW  12288               // RTOT*CO, theta floats per (t,n)

// ---------------- device scratch (static; no allocations) ----------------
__device__ float g_supports[(size_t)T_ * N_ * N_];          // 12.6 MB
__device__ float g_diag[T_ * N_];
__device__ float g_y1[(size_t)B_ * T_ * N_ * CI];           // 50 MB
__device__ float g_theta[(size_t)T_ * N_ * THW];            // 302 MB
__device__ float g_biasn[T_ * N_ * CO];                     // 1.5 MB

// ================= K1: adaptive adjacency (softmax(relu(E E^T))) + diag ===
__global__ void __launch_bounds__(256) supports_kernel(const float* __restrict__ emb) {
    __shared__ float embs[N_ * E_];           // 20 KB
    const int t = blockIdx.x;
    const float* et = emb + (size_t)t * N_ * E_;
    for (int i = threadIdx.x; i < N_ * E_; i += 256) embs[i] = et[i];
    __syncthreads();

    const int warp = threadIdx.x >> 5, lane = threadIdx.x & 31;
    for (int rr = 0; rr < 4; rr++) {
        const int n = blockIdx.y * 32 + warp * 4 + rr;
        float en[E_];
        #pragma unroll
        for (int d = 0; d < E_; d++) en[d] = embs[n * E_ + d];

        float v[16];
        #pragma unroll
        for (int j = 0; j < 16; j++) {
            const int s = lane + j * 32;
            float sc = 0.f;
            #pragma unroll
            for (int d = 0; d < E_; d++) sc = fmaf(en[d], embs[s * E_ + d], sc);
            v[j] = sc > 0.f ? sc : 0.f;      // relu
        }
        float mx = v[0];
        #pragma unroll
        for (int j = 1; j < 16; j++) mx = fmaxf(mx, v[j]);
        #pragma unroll
        for (int off = 16; off > 0; off >>= 1)
            mx = fmaxf(mx, __shfl_xor_sync(0xffffffffu, mx, off));
        float sum = 0.f;
        #pragma unroll
        for (int j = 0; j < 16; j++) { v[j] = expf(v[j] - mx); sum += v[j]; }
        #pragma unroll
        for (int off = 16; off > 0; off >>= 1)
            sum += __shfl_xor_sync(0xffffffffu, sum, off);
        const float inv = 1.f / sum;

        float* row = g_supports + ((size_t)t * N_ + n) * N_;
        #pragma unroll
        for (int j = 0; j < 16; j++) {
            const int s = lane + j * 32;
            const float p = v[j] * inv;
            row[s] = p;
            if (s == n) g_diag[t * N_ + n] = p;
        }
    }
}

// ===== K2: Y[t][512 x (B*64)] = supports[t] @ X — two b's folded into N ===
// CTA tile 128x128, K-step 32, 256 threads, 8x8 microtile.
// Register double-buffer: next tile prefetched via LDG during compute phase.
#define MT 128
#define NT 128
#define KT 32
__global__ void __launch_bounds__(256) y1_kernel(const float* __restrict__ x) {
    __shared__ float As[KT * 132];   // transposed: As[k*132 + m], pad 132
    __shared__ float Bs[KT * NT];    // [k][c], c = b_local*64 + cc
    const int m0 = blockIdx.x * MT;
    const int bp = blockIdx.y;       // b-pair: b = bp*2 + b_local
    const int t  = blockIdx.z;
    const float* A = g_supports + (size_t)t * N_ * N_;
    const int tid = threadIdx.x;
    const int tx = tid & 15, ty = tid >> 4;     // tx: 8-col group, ty: 8-row group

    // precomputed per-thread load coordinates
    int a_chunk[4], a_row[4];
    const float* b_src[4];           // base (k-row 0) pointers for B loads
    int b_col[4], b_row[4];
    #pragma unroll
    for (int i = 0; i < 4; i++) {
        const int idx = tid + i * 256;
        a_chunk[i] = idx & 7;  a_row[i] = idx >> 3;
        const int col4 = idx & 31;  b_row[i] = idx >> 5;
        const int c = col4 * 4;
        const int b = bp * 2 + (c >> 6);
        b_col[i] = c;
        b_src[i] = x + ((((size_t)b * T_ + t) * N_) * CI) + (c & 63);
    }

    float acc[8][8];
    #pragma unroll
    for (int i = 0; i < 8; i++)
        #pragma unroll
        for (int j = 0; j < 8; j++) acc[i][j] = 0.f;

    // prologue: prefetch tile 0 into registers
    float4 ra[4], rb[4];
    #pragma unroll
    for (int i = 0; i < 4; i++)
        ra[i] = *(const float4*)(A + (size_t)(m0 + a_row[i]) * N_ + a_chunk[i] * 4);
    #pragma unroll
    for (int i = 0; i < 4; i++)
        rb[i] = *(const float4*)(b_src[i] + (size_t)b_row[i] * CI);

    for (int k0 = 0; k0 < N_; k0 += KT) {
        // store current tile registers -> smem (A transposed)
        #pragma unroll
        for (int i = 0; i < 4; i++) {
            const int ch = a_chunk[i], r = a_row[i];
            As[(ch * 4 + 0) * 132 + r] = ra[i].x;
            As[(ch * 4 + 1) * 132 + r] = ra[i].y;
            As[(ch * 4 + 2) * 132 + r] = ra[i].z;
            As[(ch * 4 + 3) * 132 + r] = ra[i].w;
        }
        #pragma unroll
        for (int i = 0; i < 4; i++)
            *(float4*)&Bs[b_row[i] * NT + b_col[i]] = rb[i];
        __syncthreads();

        // prefetch next tile (LDG in flight across the whole compute phase)
        const int k1 = k0 + KT;
        if (k1 < N_) {
            #pragma unroll
            for (int i = 0; i < 4; i++)
                ra[i] = *(const float4*)(A + (size_t)(m0 + a_row[i]) * N_ + k1 + a_chunk[i] * 4);
            #pragma unroll
            for (int i = 0; i < 4; i++)
                rb[i] = *(const float4*)(b_src[i] + (size_t)(k1 + b_row[i]) * CI);
        }

        const float4* As4 = (const float4*)As;     // row stride 33 float4
        const float4* Bs4 = (const float4*)Bs;     // row stride 32 float4
        #pragma unroll
        for (int k = 0; k < KT; k++) {
            float4 a0 = As4[k * 33 + ty * 2];
            float4 a1 = As4[k * 33 + ty * 2 + 1];
            float4 c0 = Bs4[k * 32 + tx * 2];
            float4 c1 = Bs4[k * 32 + tx * 2 + 1];
            float ar[8] = {a0.x, a0.y, a0.z, a0.w, a1.x, a1.y, a1.z, a1.w};
            float br[8] = {c0.x, c0.y, c0.z, c0.w, c1.x, c1.y, c1.z, c1.w};
            #pragma unroll
            for (int i = 0; i < 8; i++)
                #pragma unroll
                for (int j = 0; j < 8; j++)
                    acc[i][j] = fmaf(ar[i], br[j], acc[i][j]);
        }
        __syncthreads();
    }
    #pragma unroll
    for (int j4 = 0; j4 < 2; j4++) {
        const int c = tx * 8 + j4 * 4;
        const int b = bp * 2 + (c >> 6);
        const int cc = c & 63;
        float* Y = g_y1 + (((size_t)b * T_ + t) * N_ + m0 + ty * 8) * CI + cc;
        #pragma unroll
        for (int i = 0; i < 8; i++) {
            float4 o = {acc[i][j4 * 4 + 0], acc[i][j4 * 4 + 1],
                        acc[i][j4 * 4 + 2], acc[i][j4 * 4 + 3]};
            *(float4*)(Y + (size_t)i * CI) = o;
        }
    }
}

// ===== K3: theta[t,n,:] = emb[t,n,:] @ W[t]  (+ per-node bias)  ===========
__global__ void __launch_bounds__(256) theta_kernel(const float* __restrict__ emb,
                                                    const float* __restrict__ Wp,
                                                    const float* __restrict__ bp) {
    __shared__ float embs[128 * E_];
    const int t = blockIdx.x, tile = blockIdx.y, nb = blockIdx.z;
    const int tid = threadIdx.x;

    float4 w[E_];
    const float* Wt = Wp + (size_t)t * E_ * THW + tile * 1024 + tid * 4;
    #pragma unroll
    for (int d = 0; d < E_; d++) w[d] = *(const float4*)(Wt + (size_t)d * THW);

    const int n0 = nb * 128;
    const float* et = emb + ((size_t)t * N_ + n0) * E_;
    for (int i = tid; i < 128 * E_; i += 256) embs[i] = et[i];
    __syncthreads();

    float* outp = g_theta + ((size_t)t * N_ + n0) * THW + tile * 1024 + tid * 4;
    for (int nn = 0; nn < 128; nn++) {
        float4 acc = {0.f, 0.f, 0.f, 0.f};
        #pragma unroll
        for (int d = 0; d < E_; d++) {
            const float e = embs[nn * E_ + d];
            acc.x = fmaf(e, w[d].x, acc.x);
            acc.y = fmaf(e, w[d].y, acc.y);
            acc.z = fmaf(e, w[d].z, acc.z);
            acc.w = fmaf(e, w[d].w, acc.w);
        }
        *(float4*)(outp + (size_t)nn * THW) = acc;
    }

    if (tile == 0) {   // bias[t,n,o] = sum_d emb * bias_pool
        const float* bt = bp + (size_t)t * E_ * CO;
        for (int i = tid; i < 128 * CO; i += 256) {
            const int nn = i >> 6, o = i & 63;
            float acc = 0.f;
            #pragma unroll
            for (int d = 0; d < E_; d++)
                acc = fmaf(embs[nn * E_ + d], bt[d * CO + o], acc);
            g_biasn[(t * N_ + n0 + nn) * CO + o] = acc;
        }
    }
}

// ===== K4: out[b,t,n,:] = relu( xg[b](192) @ theta_n(192x64) + bias ) =====
#define XPAD 36
#define SMEM_K4 ((THW + 3 * CI * XPAD) * 4)   // 76800 B
__global__ void __launch_bounds__(128) out_kernel(const float* __restrict__ x,
                                                  float* __restrict__ out) {
    extern __shared__ float sm[];
    float* th  = sm;                       // 12288 floats [r][o]
    float* xsT = th + THW;                 // [c][b] padded to 36
    float* ysT = xsT + CI * XPAD;
    float* zsT = ysT + CI * XPAD;
    const int t = blockIdx.x, n = blockIdx.y;
    const int tid = threadIdx.x;

    const float4* tg = (const float4*)(g_theta + ((size_t)t * N_ + n) * THW);
    float4* th4 = (float4*)th;
    for (int i = tid; i < THW / 4; i += 128) th4[i] = tg[i];

    const float dg = g_diag[t * N_ + n];
    for (int i = tid; i < B_ * CI; i += 128) {
        const int b = i >> 6, c = i & 63;
        const size_t off = (((size_t)b * T_ + t) * N_ + n) * CI + c;
        const float xv = x[off];
        const float yv = g_y1[off];
        xsT[c * XPAD + b] = xv;
        ysT[c * XPAD + b] = yv;
        zsT[c * XPAD + b] = 2.f * dg * yv - xv;   // S2 row applied to x
    }
    __syncthreads();

    const int tx = tid & 15, ty = tid >> 4;       // tx: o-quad, ty: b-quad
    const int o0 = tx * 4, b0 = ty * 4;
    float acc[4][4];
    #pragma unroll
    for (int i = 0; i < 4; i++)
        #pragma unroll
        for (int j = 0; j < 4; j++) acc[i][j] = 0.f;

    const float* segs[3] = {xsT, ysT, zsT};
    #pragma unroll
    for (int s = 0; s < 3; s++) {
        const float* xg = segs[s];
        const float4* ths = (const float4*)(th + s * CI * CO);
        #pragma unroll 8
        for (int rr = 0; rr < CI; rr++) {
            float4 tv = ths[rr * 16 + tx];
            float4 xv = *(const float4*)(xg + rr * XPAD + b0);
            float xr[4] = {xv.x, xv.y, xv.z, xv.w};
            float tr[4] = {tv.x, tv.y, tv.z, tv.w};
            #pragma unroll
            for (int i = 0; i < 4; i++)
                #pragma unroll
                for (int j = 0; j < 4; j++)
                    acc[i][j] = fmaf(xr[i], tr[j], acc[i][j]);
        }
    }

    float4 bv = *(const float4*)(g_biasn + ((size_t)t * N_ + n) * CO + o0);
    float br[4] = {bv.x, bv.y, bv.z, bv.w};
    #pragma unroll
    for (int i = 0; i < 4; i++) {
        const int b = b0 + i;
        float4 o;
        o.x = fmaxf(acc[i][0] + br[0], 0.f);
        o.y = fmaxf(acc[i][1] + br[1], 0.f);
        o.z = fmaxf(acc[i][2] + br[2], 0.f);
        o.w = fmaxf(acc[i][3] + br[3], 0.f);
        *(float4*)(out + (((size_t)b * T_ + t) * N_ + n) * CO + o0) = o;
    }
}

// =========================================================================
extern "C" void kernel_launch(void* const* d_in, const int* in_sizes, int n_in,
                              void* d_out, int out_size) {
    const float* x   = (const float*)d_in[0];   // [B,T,N,Ci]
    const float* emb = (const float*)d_in[1];   // [T,N,E]
    const float* Wp  = (const float*)d_in[2];   // [T,E,K,Ci,Co]
    const float* bp  = (const float*)d_in[3];   // [T,E,Co]
    float* out = (float*)d_out;                 // [B,T,N,Co]

    supports_kernel<<<dim3(T_, 16), 256>>>(emb);
    y1_kernel<<<dim3(N_ / MT, B_ / 2, T_), 256>>>(x);
    theta_kernel<<<dim3(T_, 12, 4), 256>>>(emb, Wp, bp);

    cudaFuncSetAttribute(out_kernel, cudaFuncAttributeMaxDynamicSharedMemorySize, SMEM_K4);
    out_kernel<<<dim3(T_, N_), 128, SMEM_K4>>>(x, out);
}

// round 5
// speedup vs baseline: 1.1695x; 1.1695x over previous
#include <cuda_runtime.h>

#define B_   32
#define T_   12
#define N_   512
#define E_   10
#define CI   64
#define CO   64
#define RTOT 192                 // K*CI
#define THW  12288               // RTOT*CO, theta floats per (t,n)

// ---------------- device scratch (static; no allocations) ----------------
__device__ float g_supports[(size_t)T_ * N_ * N_];          // 12.6 MB
__device__ float g_diag[T_ * N_];
__device__ float g_y1[(size_t)B_ * T_ * N_ * CI];           // 50 MB
__device__ float g_theta[(size_t)T_ * N_ * THW];            // 302 MB
__device__ float g_biasn[T_ * N_ * CO];                     // 1.5 MB

// ================= K1: adaptive adjacency (softmax(relu(E E^T))) + diag ===
__global__ void __launch_bounds__(256) supports_kernel(const float* __restrict__ emb) {
    __shared__ float embs[N_ * E_];           // 20 KB
    const int t = blockIdx.x;
    const float* et = emb + (size_t)t * N_ * E_;
    for (int i = threadIdx.x; i < N_ * E_; i += 256) embs[i] = et[i];
    __syncthreads();

    const int warp = threadIdx.x >> 5, lane = threadIdx.x & 31;
    for (int rr = 0; rr < 4; rr++) {
        const int n = blockIdx.y * 32 + warp * 4 + rr;
        float en[E_];
        #pragma unroll
        for (int d = 0; d < E_; d++) en[d] = embs[n * E_ + d];

        float v[16];
        #pragma unroll
        for (int j = 0; j < 16; j++) {
            const int s = lane + j * 32;
            float sc = 0.f;
            #pragma unroll
            for (int d = 0; d < E_; d++) sc = fmaf(en[d], embs[s * E_ + d], sc);
            v[j] = sc > 0.f ? sc : 0.f;      // relu
        }
        float mx = v[0];
        #pragma unroll
        for (int j = 1; j < 16; j++) mx = fmaxf(mx, v[j]);
        #pragma unroll
        for (int off = 16; off > 0; off >>= 1)
            mx = fmaxf(mx, __shfl_xor_sync(0xffffffffu, mx, off));
        float sum = 0.f;
        #pragma unroll
        for (int j = 0; j < 16; j++) { v[j] = expf(v[j] - mx); sum += v[j]; }
        #pragma unroll
        for (int off = 16; off > 0; off >>= 1)
            sum += __shfl_xor_sync(0xffffffffu, sum, off);
        const float inv = 1.f / sum;

        float* row = g_supports + ((size_t)t * N_ + n) * N_;
        #pragma unroll
        for (int j = 0; j < 16; j++) {
            const int s = lane + j * 32;
            const float p = v[j] * inv;
            row[s] = p;
            if (s == n) g_diag[t * N_ + n] = p;
        }
    }
}

// ===== K2: Y[t][512 x (B*64)] = supports[t] @ X — two b's folded into N ===
// CTA tile 128x128, K-step 32, 256 threads, 8x8 microtile, reg prefetch.
#define MT 128
#define NT 128
#define KT 32
__global__ void __launch_bounds__(256) y1_kernel(const float* __restrict__ x) {
    __shared__ float As[KT * 132];   // transposed: As[k*132 + m], pad 132
    __shared__ float Bs[KT * NT];    // [k][c], c = b_local*64 + cc
    const int m0 = blockIdx.x * MT;
    const int bp = blockIdx.y;       // b-pair: b = bp*2 + b_local
    const int t  = blockIdx.z;
    const float* A = g_supports + (size_t)t * N_ * N_;
    const int tid = threadIdx.x;
    const int tx = tid & 15, ty = tid >> 4;

    int a_chunk[4], a_row[4];
    const float* b_src[4];
    int b_col[4], b_row[4];
    #pragma unroll
    for (int i = 0; i < 4; i++) {
        const int idx = tid + i * 256;
        a_chunk[i] = idx & 7;  a_row[i] = idx >> 3;
        const int col4 = idx & 31;  b_row[i] = idx >> 5;
        const int c = col4 * 4;
        const int b = bp * 2 + (c >> 6);
        b_col[i] = c;
        b_src[i] = x + ((((size_t)b * T_ + t) * N_) * CI) + (c & 63);
    }

    float acc[8][8];
    #pragma unroll
    for (int i = 0; i < 8; i++)
        #pragma unroll
        for (int j = 0; j < 8; j++) acc[i][j] = 0.f;

    float4 ra[4], rb[4];
    #pragma unroll
    for (int i = 0; i < 4; i++)
        ra[i] = *(const float4*)(A + (size_t)(m0 + a_row[i]) * N_ + a_chunk[i] * 4);
    #pragma unroll
    for (int i = 0; i < 4; i++)
        rb[i] = *(const float4*)(b_src[i] + (size_t)b_row[i] * CI);

    for (int k0 = 0; k0 < N_; k0 += KT) {
        #pragma unroll
        for (int i = 0; i < 4; i++) {
            const int ch = a_chunk[i], r = a_row[i];
            As[(ch * 4 + 0) * 132 + r] = ra[i].x;
            As[(ch * 4 + 1) * 132 + r] = ra[i].y;
            As[(ch * 4 + 2) * 132 + r] = ra[i].z;
            As[(ch * 4 + 3) * 132 + r] = ra[i].w;
        }
        #pragma unroll
        for (int i = 0; i < 4; i++)
            *(float4*)&Bs[b_row[i] * NT + b_col[i]] = rb[i];
        __syncthreads();

        const int k1 = k0 + KT;
        if (k1 < N_) {
            #pragma unroll
            for (int i = 0; i < 4; i++)
                ra[i] = *(const float4*)(A + (size_t)(m0 + a_row[i]) * N_ + k1 + a_chunk[i] * 4);
            #pragma unroll
            for (int i = 0; i < 4; i++)
                rb[i] = *(const float4*)(b_src[i] + (size_t)(k1 + b_row[i]) * CI);
        }

        const float4* As4 = (const float4*)As;
        const float4* Bs4 = (const float4*)Bs;
        #pragma unroll
        for (int k = 0; k < KT; k++) {
            float4 a0 = As4[k * 33 + ty * 2];
            float4 a1 = As4[k * 33 + ty * 2 + 1];
            float4 c0 = Bs4[k * 32 + tx * 2];
            float4 c1 = Bs4[k * 32 + tx * 2 + 1];
            float ar[8] = {a0.x, a0.y, a0.z, a0.w, a1.x, a1.y, a1.z, a1.w};
            float br[8] = {c0.x, c0.y, c0.z, c0.w, c1.x, c1.y, c1.z, c1.w};
            #pragma unroll
            for (int i = 0; i < 8; i++)
                #pragma unroll
                for (int j = 0; j < 8; j++)
                    acc[i][j] = fmaf(ar[i], br[j], acc[i][j]);
        }
        __syncthreads();
    }
    #pragma unroll
    for (int j4 = 0; j4 < 2; j4++) {
        const int c = tx * 8 + j4 * 4;
        const int b = bp * 2 + (c >> 6);
        const int cc = c & 63;
        float* Y = g_y1 + (((size_t)b * T_ + t) * N_ + m0 + ty * 8) * CI + cc;
        #pragma unroll
        for (int i = 0; i < 8; i++) {
            float4 o = {acc[i][j4 * 4 + 0], acc[i][j4 * 4 + 1],
                        acc[i][j4 * 4 + 2], acc[i][j4 * 4 + 3]};
            *(float4*)(Y + (size_t)i * CI) = o;
        }
    }
}

// ===== K3: theta[t,n,:] = emb[t,n,:] @ W[t]  (+ per-node bias)  ===========
__global__ void __launch_bounds__(256) theta_kernel(const float* __restrict__ emb,
                                                    const float* __restrict__ Wp,
                                                    const float* __restrict__ bp) {
    __shared__ float embs[128 * E_];
    const int t = blockIdx.x, tile = blockIdx.y, nb = blockIdx.z;
    const int tid = threadIdx.x;

    float4 w[E_];
    const float* Wt = Wp + (size_t)t * E_ * THW + tile * 1024 + tid * 4;
    #pragma unroll
    for (int d = 0; d < E_; d++) w[d] = *(const float4*)(Wt + (size_t)d * THW);

    const int n0 = nb * 128;
    const float* et = emb + ((size_t)t * N_ + n0) * E_;
    for (int i = tid; i < 128 * E_; i += 256) embs[i] = et[i];
    __syncthreads();

    float* outp = g_theta + ((size_t)t * N_ + n0) * THW + tile * 1024 + tid * 4;
    for (int nn = 0; nn < 128; nn++) {
        float4 acc = {0.f, 0.f, 0.f, 0.f};
        #pragma unroll
        for (int d = 0; d < E_; d++) {
            const float e = embs[nn * E_ + d];
            acc.x = fmaf(e, w[d].x, acc.x);
            acc.y = fmaf(e, w[d].y, acc.y);
            acc.z = fmaf(e, w[d].z, acc.z);
            acc.w = fmaf(e, w[d].w, acc.w);
        }
        *(float4*)(outp + (size_t)nn * THW) = acc;
    }

    if (tile == 0) {   // bias[t,n,o] = sum_d emb * bias_pool
        const float* bt = bp + (size_t)t * E_ * CO;
        for (int i = tid; i < 128 * CO; i += 256) {
            const int nn = i >> 6, o = i & 63;
            float acc = 0.f;
            #pragma unroll
            for (int d = 0; d < E_; d++)
                acc = fmaf(embs[nn * E_ + d], bt[d * CO + o], acc);
            g_biasn[(t * N_ + n0 + nn) * CO + o] = acc;
        }
    }
}

// ===== K4: out[b,t,n,:] = relu( xg[b](192) @ theta_n(192x64) + bias ) =====
// Theta streamed in 3 chunks of 64 rows (16KB) -> smem 44KB -> 5 CTAs/SM.
#define XPAD 36
#define TCH  (CI * CO)                       // 4096 floats per chunk
#define SMEM_K4 ((TCH + 3 * CI * XPAD) * 4)  // 44.0 KB
__global__ void __launch_bounds__(128) out_kernel(const float* __restrict__ x,
                                                  float* __restrict__ out) {
    extern __shared__ float sm[];
    float* th  = sm;                       // 4096 floats, one k-segment [r][o]
    float* xsT = th + TCH;                 // [c][b] padded to 36
    float* ysT = xsT + CI * XPAD;
    float* zsT = ysT + CI * XPAD;
    const int t = blockIdx.x, n = blockIdx.y;
    const int tid = threadIdx.x;

    const float dg = g_diag[t * N_ + n];
    for (int i = tid; i < B_ * CI; i += 128) {
        const int b = i >> 6, c = i & 63;
        const size_t off = (((size_t)b * T_ + t) * N_ + n) * CI + c;
        const float xv = x[off];
        const float yv = g_y1[off];
        xsT[c * XPAD + b] = xv;
        ysT[c * XPAD + b] = yv;
        zsT[c * XPAD + b] = 2.f * dg * yv - xv;   // S2 row applied to x
    }

    const int tx = tid & 15, ty = tid >> 4;       // tx: o-quad, ty: b-quad
    const int o0 = tx * 4, b0 = ty * 4;
    float acc[4][4];
    #pragma unroll
    for (int i = 0; i < 4; i++)
        #pragma unroll
        for (int j = 0; j < 4; j++) acc[i][j] = 0.f;

    const float4* tg = (const float4*)(g_theta + ((size_t)t * N_ + n) * THW);
    float4* th4w = (float4*)th;
    const float* segs[3] = {xsT, ysT, zsT};

    #pragma unroll
    for (int s = 0; s < 3; s++) {
        __syncthreads();                          // protect th from prev seg readers
        // load segment s: 1024 float4, 8 per thread, coalesced
        #pragma unroll
        for (int j = 0; j < 8; j++)
            th4w[tid + j * 128] = tg[s * (TCH / 4) + tid + j * 128];
        __syncthreads();

        const float* xg = segs[s];
        const float4* ths = (const float4*)th;
        #pragma unroll 8
        for (int rr = 0; rr < CI; rr++) {
            float4 tv = ths[rr * 16 + tx];
            float4 xv = *(const float4*)(xg + rr * XPAD + b0);
            float xr[4] = {xv.x, xv.y, xv.z, xv.w};
            float tr[4] = {tv.x, tv.y, tv.z, tv.w};
            #pragma unroll
            for (int i = 0; i < 4; i++)
                #pragma unroll
                for (int j = 0; j < 4; j++)
                    acc[i][j] = fmaf(xr[i], tr[j], acc[i][j]);
        }
    }

    float4 bv = *(const float4*)(g_biasn + ((size_t)t * N_ + n) * CO + o0);
    float br[4] = {bv.x, bv.y, bv.z, bv.w};
    #pragma unroll
    for (int i = 0; i < 4; i++) {
        const int b = b0 + i;
        float4 o;
        o.x = fmaxf(acc[i][0] + br[0], 0.f);
        o.y = fmaxf(acc[i][1] + br[1], 0.f);
        o.z = fmaxf(acc[i][2] + br[2], 0.f);
        o.w = fmaxf(acc[i][3] + br[3], 0.f);
        *(float4*)(out + (((size_t)b * T_ + t) * N_ + n) * CO + o0) = o;
    }
}

// =========================================================================
extern "C" void kernel_launch(void* const* d_in, const int* in_sizes, int n_in,
                              void* d_out, int out_size) {
    const float* x   = (const float*)d_in[0];   // [B,T,N,Ci]
    const float* emb = (const float*)d_in[1];   // [T,N,E]
    const float* Wp  = (const float*)d_in[2];   // [T,E,K,Ci,Co]
    const float* bp  = (const float*)d_in[3];   // [T,E,Co]
    float* out = (float*)d_out;                 // [B,T,N,Co]

    supports_kernel<<<dim3(T_, 16), 256>>>(emb);
    y1_kernel<<<dim3(N_ / MT, B_ / 2, T_), 256>>>(x);
    theta_kernel<<<dim3(T_, 12, 4), 256>>>(emb, Wp, bp);

    cudaFuncSetAttribute(out_kernel, cudaFuncAttributeMaxDynamicSharedMemorySize, SMEM_K4);
    out_kernel<<<dim3(T_, N_), 128, SMEM_K4>>>(x, out);
}

// round 13
// speedup vs baseline: 1.7158x; 1.4671x over previous
#include <cuda_runtime.h>
#include <cuda_bf16.h>
#include <cstdint>

#define B_   32
#define T_   12
#define N_   512
#define E_   10
#define CI   64
#define CO   64
#define RTOT 192                 // K*CI
#define THW  12288               // RTOT*CO, theta floats per (t,n)

// ---------------- device scratch (static; no allocations) ----------------
__device__ float g_supports[(size_t)T_ * N_ * N_];          // 12.6 MB
__device__ float g_diag[T_ * N_];
__device__ float g_y1[(size_t)B_ * T_ * N_ * CI];           // 50 MB
__device__ float g_theta[(size_t)T_ * N_ * THW];            // 302 MB
__device__ float g_biasn[T_ * N_ * CO];                     // 1.5 MB

// ================= K1: adaptive adjacency (softmax(relu(E E^T))) + diag ===
__global__ void __launch_bounds__(256) supports_kernel(const float* __restrict__ emb) {
    __shared__ float embs[N_ * E_];           // 20 KB
    const int t = blockIdx.x;
    const float* et = emb + (size_t)t * N_ * E_;
    for (int i = threadIdx.x; i < N_ * E_; i += 256) embs[i] = et[i];
    __syncthreads();

    const int warp = threadIdx.x >> 5, lane = threadIdx.x & 31;
    for (int rr = 0; rr < 4; rr++) {
        const int n = blockIdx.y * 32 + warp * 4 + rr;
        float en[E_];
        #pragma unroll
        for (int d = 0; d < E_; d++) en[d] = embs[n * E_ + d];

        float v[16];
        #pragma unroll
        for (int j = 0; j < 16; j++) {
            const int s = lane + j * 32;
            float sc = 0.f;
            #pragma unroll
            for (int d = 0; d < E_; d++) sc = fmaf(en[d], embs[s * E_ + d], sc);
            v[j] = sc > 0.f ? sc : 0.f;      // relu
        }
        float mx = v[0];
        #pragma unroll
        for (int j = 1; j < 16; j++) mx = fmaxf(mx, v[j]);
        #pragma unroll
        for (int off = 16; off > 0; off >>= 1)
            mx = fmaxf(mx, __shfl_xor_sync(0xffffffffu, mx, off));
        float sum = 0.f;
        #pragma unroll
        for (int j = 0; j < 16; j++) { v[j] = expf(v[j] - mx); sum += v[j]; }
        #pragma unroll
        for (int off = 16; off > 0; off >>= 1)
            sum += __shfl_xor_sync(0xffffffffu, sum, off);
        const float inv = 1.f / sum;

        float* row = g_supports + ((size_t)t * N_ + n) * N_;
        #pragma unroll
        for (int j = 0; j < 16; j++) {
            const int s = lane + j * 32;
            const float p = v[j] * inv;
            row[s] = p;
            if (s == n) g_diag[t * N_ + n] = p;
        }
    }
}

// ===== helpers: bf16 split (hi = rn-to-bf16, lo = trunc(residual)) ======
__device__ __forceinline__ void split2(float v0, float v1, uint32_t& hi, uint32_t& lo) {
    uint32_t u0 = __float_as_uint(v0), u1 = __float_as_uint(v1);
    uint32_t r0 = u0 + 0x7FFFu + ((u0 >> 16) & 1u);   // round-to-nearest-even bf16
    uint32_t r1 = u1 + 0x7FFFu + ((u1 >> 16) & 1u);
    hi = __byte_perm(r0, r1, 0x7632);                 // {hi16(r0), hi16(r1)}
    float l0 = v0 - __uint_as_float(r0 & 0xFFFF0000u);
    float l1 = v1 - __uint_as_float(r1 & 0xFFFF0000u);
    lo = __byte_perm(__float_as_uint(l0), __float_as_uint(l1), 0x7632);
}

__device__ __forceinline__ void mma_bf16(float* c,
        uint32_t a0, uint32_t a1, uint32_t a2, uint32_t a3,
        uint32_t b0, uint32_t b1) {
    asm volatile(
        "mma.sync.aligned.m16n8k16.row.col.f32.bf16.bf16.f32 "
        "{%0,%1,%2,%3}, {%4,%5,%6,%7}, {%8,%9}, {%0,%1,%2,%3};"
        : "+f"(c[0]), "+f"(c[1]), "+f"(c[2]), "+f"(c[3])
        : "r"(a0), "r"(a1), "r"(a2), "r"(a3), "r"(b0), "r"(b1));
}

// ===== K2: Y[t][512 x (B*64)] = supports[t] @ X — bf16 split-4 mma ======
// CTA tile 128x128, KT=32, 256 threads = 8 warps (2m x 4n), warp tile 64x32.
#define MT 128
#define KT 32
#define APAD 36                  // bf16 elements per smem row (k padded)
__global__ void __launch_bounds__(256) y1_kernel(const float* __restrict__ x) {
    __shared__ __align__(16) __nv_bfloat16 As_hi[MT * APAD];
    __shared__ __align__(16) __nv_bfloat16 As_lo[MT * APAD];
    __shared__ __align__(16) __nv_bfloat16 Bs_hi[MT * APAD];
    __shared__ __align__(16) __nv_bfloat16 Bs_lo[MT * APAD];

    const int m0 = blockIdx.x * MT;
    const int bp = blockIdx.y;       // b-pair: b = bp*2 + b_local
    const int t  = blockIdx.z;
    const float* A = g_supports + (size_t)t * N_ * N_;
    const int tid  = threadIdx.x;
    const int warp = tid >> 5, lane = tid & 31;
    const int g = lane >> 2, tig = lane & 3;
    const int wm = warp >> 2, wn = warp & 3;       // warp grid 2(m) x 4(n)
    const int mb = wm * 64, nb = wn * 32;

    // A staging map: 4 float4/thread, chunk = k-quad (0..7), m = row (0..127)
    int a_chunk[4], a_m[4];
    // B staging map: 4 units/thread, each = 4 k's of one column n
    int b_n[4], b_kg[4];
    const float* b_ptr[4];
    #pragma unroll
    for (int i = 0; i < 4; i++) {
        const int idx = tid + i * 256;
        a_chunk[i] = idx & 7;  a_m[i] = idx >> 3;
        const int n = idx & 127, kg = idx >> 7;
        b_n[i] = n;  b_kg[i] = kg;
        const int b = bp * 2 + (n >> 6);
        b_ptr[i] = x + (((size_t)b * T_ + t) * N_) * CI + (n & 63);
    }

    float acc[4][4][4];
    #pragma unroll
    for (int i = 0; i < 4; i++)
        #pragma unroll
        for (int j = 0; j < 4; j++)
            #pragma unroll
            for (int q = 0; q < 4; q++) acc[i][j][q] = 0.f;

    // prologue: prefetch tile 0 (raw fp32) into registers
    float4 ra[4];
    float  rb[4][4];
    #pragma unroll
    for (int i = 0; i < 4; i++)
        ra[i] = *(const float4*)(A + (size_t)(m0 + a_m[i]) * N_ + a_chunk[i] * 4);
    #pragma unroll
    for (int i = 0; i < 4; i++)
        #pragma unroll
        for (int j = 0; j < 4; j++)
            rb[i][j] = b_ptr[i][(size_t)(b_kg[i] * 4 + j) * CI];

    for (int k0 = 0; k0 < N_; k0 += KT) {
        // convert + store staged tile to smem (hi/lo bf16)
        #pragma unroll
        for (int i = 0; i < 4; i++) {
            uint32_t h01, l01, h23, l23;
            split2(ra[i].x, ra[i].y, h01, l01);
            split2(ra[i].z, ra[i].w, h23, l23);
            const int o = a_m[i] * APAD + a_chunk[i] * 4;
            *(uint2*)(As_hi + o) = make_uint2(h01, h23);
            *(uint2*)(As_lo + o) = make_uint2(l01, l23);
        }
        #pragma unroll
        for (int i = 0; i < 4; i++) {
            uint32_t h01, l01, h23, l23;
            split2(rb[i][0], rb[i][1], h01, l01);
            split2(rb[i][2], rb[i][3], h23, l23);
            const int o = b_n[i] * APAD + b_kg[i] * 4;
            *(uint2*)(Bs_hi + o) = make_uint2(h01, h23);
            *(uint2*)(Bs_lo + o) = make_uint2(l01, l23);
        }
        __syncthreads();

        // prefetch next tile
        const int k1 = k0 + KT;
        if (k1 < N_) {
            #pragma unroll
            for (int i = 0; i < 4; i++)
                ra[i] = *(const float4*)(A + (size_t)(m0 + a_m[i]) * N_ + k1 + a_chunk[i] * 4);
            #pragma unroll
            for (int i = 0; i < 4; i++)
                #pragma unroll
                for (int j = 0; j < 4; j++)
                    rb[i][j] = b_ptr[i][(size_t)(k1 + b_kg[i] * 4 + j) * CI];
        }

        // compute: 2 x k16 chunks, 16 m16n8 tiles per warp, 4 products each
        #pragma unroll
        for (int kk = 0; kk < KT; kk += 16) {
            uint32_t bh[4][2], bl[4][2];
            #pragma unroll
            for (int j = 0; j < 4; j++) {
                const int r = (nb + j * 8 + g) * APAD + kk + 2 * tig;
                bh[j][0] = *(const uint32_t*)(Bs_hi + r);
                bh[j][1] = *(const uint32_t*)(Bs_hi + r + 8);
                bl[j][0] = *(const uint32_t*)(Bs_lo + r);
                bl[j][1] = *(const uint32_t*)(Bs_lo + r + 8);
            }
            #pragma unroll
            for (int i = 0; i < 4; i++) {
                const int r0 = (mb + i * 16 + g) * APAD + kk + 2 * tig;
                const int r1 = r0 + 8 * APAD;
                const uint32_t ah0 = *(const uint32_t*)(As_hi + r0);
                const uint32_t ah1 = *(const uint32_t*)(As_hi + r1);
                const uint32_t ah2 = *(const uint32_t*)(As_hi + r0 + 8);
                const uint32_t ah3 = *(const uint32_t*)(As_hi + r1 + 8);
                const uint32_t al0 = *(const uint32_t*)(As_lo + r0);
                const uint32_t al1 = *(const uint32_t*)(As_lo + r1);
                const uint32_t al2 = *(const uint32_t*)(As_lo + r0 + 8);
                const uint32_t al3 = *(const uint32_t*)(As_lo + r1 + 8);
                #pragma unroll
                for (int j = 0; j < 4; j++) {
                    mma_bf16(acc[i][j], al0, al1, al2, al3, bl[j][0], bl[j][1]); // lo*lo
                    mma_bf16(acc[i][j], ah0, ah1, ah2, ah3, bl[j][0], bl[j][1]); // hi*lo
                    mma_bf16(acc[i][j], al0, al1, al2, al3, bh[j][0], bh[j][1]); // lo*hi
                    mma_bf16(acc[i][j], ah0, ah1, ah2, ah3, bh[j][0], bh[j][1]); // hi*hi
                }
            }
        }
        __syncthreads();
    }

    // epilogue: c0=(g,2tig) c1=(g,2tig+1) c2=(g+8,2tig) c3=(g+8,2tig+1)
    #pragma unroll
    for (int i = 0; i < 4; i++) {
        #pragma unroll
        for (int j = 0; j < 4; j++) {
            const int n_loc = nb + j * 8 + 2 * tig;
            const int b = bp * 2 + (n_loc >> 6);
            const int cc = n_loc & 63;
            const int m_glob = m0 + mb + i * 16 + g;
            float* Y0 = g_y1 + (((size_t)b * T_ + t) * N_ + m_glob) * CI + cc;
            float* Y1 = Y0 + (size_t)8 * CI;
            *(float2*)Y0 = make_float2(acc[i][j][0], acc[i][j][1]);
            *(float2*)Y1 = make_float2(acc[i][j][2], acc[i][j][3]);
        }
    }
}

// ===== K3: theta[t,n,:] = emb[t,n,:] @ W[t]  (+ per-node bias)  ===========
__global__ void __launch_bounds__(256) theta_kernel(const float* __restrict__ emb,
                                                    const float* __restrict__ Wp,
                                                    const float* __restrict__ bp) {
    __shared__ float embs[128 * E_];
    const int t = blockIdx.x, tile = blockIdx.y, nb = blockIdx.z;
    const int tid = threadIdx.x;

    float4 w[E_];
    const float* Wt = Wp + (size_t)t * E_ * THW + tile * 1024 + tid * 4;
    #pragma unroll
    for (int d = 0; d < E_; d++) w[d] = *(const float4*)(Wt + (size_t)d * THW);

    const int n0 = nb * 128;
    const float* et = emb + ((size_t)t * N_ + n0) * E_;
    for (int i = tid; i < 128 * E_; i += 256) embs[i] = et[i];
    __syncthreads();

    float* outp = g_theta + ((size_t)t * N_ + n0) * THW + tile * 1024 + tid * 4;
    for (int nn = 0; nn < 128; nn++) {
        float4 acc = {0.f, 0.f, 0.f, 0.f};
        #pragma unroll
        for (int d = 0; d < E_; d++) {
            const float e = embs[nn * E_ + d];
            acc.x = fmaf(e, w[d].x, acc.x);
            acc.y = fmaf(e, w[d].y, acc.y);
            acc.z = fmaf(e, w[d].z, acc.z);
            acc.w = fmaf(e, w[d].w, acc.w);
        }
        *(float4*)(outp + (size_t)nn * THW) = acc;
    }

    if (tile == 0) {   // bias[t,n,o] = sum_d emb * bias_pool
        const float* bt = bp + (size_t)t * E_ * CO;
        for (int i = tid; i < 128 * CO; i += 256) {
            const int nn = i >> 6, o = i & 63;
            float acc = 0.f;
            #pragma unroll
            for (int d = 0; d < E_; d++)
                acc = fmaf(embs[nn * E_ + d], bt[d * CO + o], acc);
            g_biasn[(t * N_ + n0 + nn) * CO + o] = acc;
        }
    }
}

// ===== K4: out[b,t,n,:] = relu( xg[b](192) @ theta_n(192x64) + bias ) =====
// Theta streamed in 6 chunks of 32 rows (8KB) with register double-buffer.
// smem 35.8KB; __launch_bounds__(128,6) pins 6 CTAs/SM (24 warps).
#define XPAD 36
#define TROWS 32                               // theta rows per chunk
#define TCH  (TROWS * CO)                      // 2048 floats per chunk
#define NSEG (RTOT / TROWS)                    // 6 chunks
#define SMEM_K4 ((TCH + 3 * CI * XPAD) * 4)    // 35840 B
__global__ void __launch_bounds__(128, 6) out_kernel(const float* __restrict__ x,
                                                     float* __restrict__ out) {
    extern __shared__ float sm[];
    float* th  = sm;                       // 2048 floats, one 32-row chunk [r][o]
    float* xsT = th + TCH;                 // [c][b] padded to 36
    float* ysT = xsT + CI * XPAD;
    float* zsT = ysT + CI * XPAD;
    const int t = blockIdx.x, n = blockIdx.y;
    const int tid = threadIdx.x;

    const float dg = g_diag[t * N_ + n];
    for (int i = tid; i < B_ * CI; i += 128) {
        const int b = i >> 6, c = i & 63;
        const size_t off = (((size_t)b * T_ + t) * N_ + n) * CI + c;
        const float xv = x[off];
        const float yv = g_y1[off];
        xsT[c * XPAD + b] = xv;
        ysT[c * XPAD + b] = yv;
        zsT[c * XPAD + b] = 2.f * dg * yv - xv;   // S2 row applied to x
    }

    const int tx = tid & 15, ty = tid >> 4;       // tx: o-quad, ty: b-quad
    const int o0 = tx * 4, b0 = ty * 4;
    float acc[4][4];
    #pragma unroll
    for (int i = 0; i < 4; i++)
        #pragma unroll
        for (int j = 0; j < 4; j++) acc[i][j] = 0.f;

    const float4* tg = (const float4*)(g_theta + ((size_t)t * N_ + n) * THW);
    float4* th4w = (float4*)th;
    const float* segs[3] = {xsT, ysT, zsT};

    // prefetch chunk 0 into registers (512 float4, 4 per thread)
    float4 pre[4];
    #pragma unroll
    for (int j = 0; j < 4; j++) pre[j] = tg[tid + j * 128];

    #pragma unroll
    for (int s = 0; s < NSEG; s++) {
        __syncthreads();                          // protect th from prev readers
        #pragma unroll
        for (int j = 0; j < 4; j++) th4w[tid + j * 128] = pre[j];
        __syncthreads();
        if (s + 1 < NSEG) {                       // prefetch next chunk
            #pragma unroll
            for (int j = 0; j < 4; j++)
                pre[j] = tg[(s + 1) * (TCH / 4) + tid + j * 128];
        }

        const float* xg = segs[s >> 1] + (s & 1) * TROWS * XPAD;
        const float4* ths = (const float4*)th;
        #pragma unroll 8
        for (int rr = 0; rr < TROWS; rr++) {
            float4 tv = ths[rr * 16 + tx];
            float4 xv = *(const float4*)(xg + rr * XPAD + b0);
            float xr[4] = {xv.x, xv.y, xv.z, xv.w};
            float tr[4] = {tv.x, tv.y, tv.z, tv.w};
            #pragma unroll
            for (int i = 0; i < 4; i++)
                #pragma unroll
                for (int j = 0; j < 4; j++)
                    acc[i][j] = fmaf(xr[i], tr[j], acc[i][j]);
        }
    }

    float4 bv = *(const float4*)(g_biasn + ((size_t)t * N_ + n) * CO + o0);
    float br[4] = {bv.x, bv.y, bv.z, bv.w};
    #pragma unroll
    for (int i = 0; i < 4; i++) {
        const int b = b0 + i;
        float4 o;
        o.x = fmaxf(acc[i][0] + br[0], 0.f);
        o.y = fmaxf(acc[i][1] + br[1], 0.f);
        o.z = fmaxf(acc[i][2] + br[2], 0.f);
        o.w = fmaxf(acc[i][3] + br[3], 0.f);
        *(float4*)(out + (((size_t)b * T_ + t) * N_ + n) * CO + o0) = o;
    }
}

// =========================================================================
extern "C" void kernel_launch(void* const* d_in, const int* in_sizes, int n_in,
                              void* d_out, int out_size) {
    const float* x   = (const float*)d_in[0];   // [B,T,N,Ci]
    const float* emb = (const float*)d_in[1];   // [T,N,E]
    const float* Wp  = (const float*)d_in[2];   // [T,E,K,Ci,Co]
    const float* bp  = (const float*)d_in[3];   // [T,E,Co]
    float* out = (float*)d_out;                 // [B,T,N,Co]

    supports_kernel<<<dim3(T_, 16), 256>>>(emb);
    y1_kernel<<<dim3(N_ / MT, B_ / 2, T_), 256>>>(x);
    theta_kernel<<<dim3(T_, 12, 4), 256>>>(emb, Wp, bp);

    cudaFuncSetAttribute(out_kernel, cudaFuncAttributeMaxDynamicSharedMemorySize, SMEM_K4);
    out_kernel<<<dim3(T_, N_), 128, SMEM_K4>>>(x, out);
}